// round 14
// baseline (speedup 1.0000x reference)
#include <cuda_runtime.h>
#include <cuda_fp16.h>
#include <math.h>
#include <stdint.h>

#define NB 2
#define NN 512
#define NC 128
#define O1 128
#define O2 64
#define DROPK 52         // 512 - 460
#define SW 68            // row stride in u32 words (136 fp16; ldmatrix conflict-free)
#define NROWS (NB * NN)
#define GRID 148

__device__ __forceinline__ uint32_t smem_u32(const void* p) {
    uint32_t a;
    asm("{ .reg .u64 t; cvta.to.shared.u64 t, %1; cvt.u32.u64 %0, t; }"
        : "=r"(a) : "l"(p));
    return a;
}

// pack two fp32 into fp16x2 (lo = x0, hi = x1)
__device__ __forceinline__ uint32_t pack_h2(float x0, float x1) {
    uint32_t r;
    asm("cvt.rn.f16x2.f32 %0, %1, %2;" : "=r"(r) : "f"(x1), "f"(x0));
    return r;
}
// pack + residual (for weights)
__device__ __forceinline__ void split2h(float x0, float x1, uint32_t& hp, uint32_t& lp) {
    hp = pack_h2(x0, x1);
    __half2 hb = *reinterpret_cast<__half2*>(&hp);
    float l0 = x0 - __half2float(hb.x);
    float l1 = x1 - __half2float(hb.y);
    lp = pack_h2(l0, l1);
}

__device__ __forceinline__ void mma16816(float* c, const uint32_t* a, const uint32_t* b) {
    asm volatile(
        "mma.sync.aligned.m16n8k16.row.col.f32.f16.f16.f32 "
        "{%0,%1,%2,%3}, {%4,%5,%6,%7}, {%8,%9}, {%0,%1,%2,%3};"
        : "+f"(c[0]), "+f"(c[1]), "+f"(c[2]), "+f"(c[3])
        : "r"(a[0]), "r"(a[1]), "r"(a[2]), "r"(a[3]), "r"(b[0]), "r"(b[1]));
}

__device__ __forceinline__ void ldsm4(uint32_t* r, uint32_t saddr) {
    asm volatile("ldmatrix.sync.aligned.m8n8.x4.shared.b16 {%0,%1,%2,%3}, [%4];"
                 : "=r"(r[0]), "=r"(r[1]), "=r"(r[2]), "=r"(r[3]) : "r"(saddr));
}

// ---------------- folded + packed weights (prelude output) ----------------
__device__ uint32_t g_w1h[O1 * SW];
__device__ uint32_t g_w1l[O1 * SW];
__device__ uint32_t g_w2h[O2 * SW];
__device__ uint32_t g_w2l[O2 * SW];
__device__ float g_b1f[O1];
__device__ float g_b2f[O2];
__device__ float g_W3f[O2];
__device__ float g_b3f;
__device__ int g_row_ctr;       // work-stealing counter (reset by prelude)
__device__ int g_bar;           // global barrier counter (reset by prelude)
// raw sigmoid(logits); fully populated (direct + transposed mirror writes).
__device__ float g_sg[(size_t)NB * NN * NN];

__global__ void prelude_kernel(
    const float* __restrict__ W1, const float* __restrict__ g1,
    const float* __restrict__ be1, const float* __restrict__ m1,
    const float* __restrict__ v1,
    const float* __restrict__ W2, const float* __restrict__ g2,
    const float* __restrict__ be2, const float* __restrict__ m2,
    const float* __restrict__ v2,
    const float* __restrict__ W3, const float* __restrict__ b3)
{
    __shared__ float s1[O1], s2[O2];
    int t = threadIdx.x;
    if (t < O1) {
        float s = g1[t] / sqrtf(v1[t] + 1e-5f);
        s1[t] = s;
        if (blockIdx.x == 0) g_b1f[t] = be1[t] - m1[t] * s;
    } else if (t < O1 + O2) {
        int o = t - O1;
        float s = g2[o] / sqrtf(v2[o] + 1e-5f);
        s2[o] = s;
        if (blockIdx.x == 0) g_b2f[o] = be2[o] - m2[o] * s;
    } else if (t < O1 + 2 * O2) {
        int o = t - (O1 + O2);
        if (blockIdx.x == 0) {
            g_W3f[o] = W3[o];
            if (o == 0) { g_b3f = b3[0]; g_row_ctr = GRID; g_bar = 0; }
        }
    }
    __syncthreads();
    int stride = blockDim.x * gridDim.x;
    int base = blockIdx.x * blockDim.x + t;
    for (int idx = base; idx < O1 * 64; idx += stride) {
        int o = idx >> 6, cp = idx & 63;
        float v0 = W1[o * NC + 2 * cp] * s1[o];
        float v1v = W1[o * NC + 2 * cp + 1] * s1[o];
        uint32_t hp, lp;
        split2h(v0, v1v, hp, lp);
        g_w1h[o * SW + cp] = hp;
        g_w1l[o * SW + cp] = lp;
    }
    for (int idx = base; idx < O2 * 64; idx += stride) {
        int n = idx >> 6, cp = idx & 63;
        float v0 = W2[n * O1 + 2 * cp] * s2[n];
        float v1v = W2[n * O1 + 2 * cp + 1] * s2[n];
        uint32_t hp, lp;
        split2h(v0, v1v, hp, lp);
        g_w2h[n * SW + cp] = hp;
        g_w2l[n * SW + cp] = lp;
    }
}

// ---------------- SMEM layout (u32 word offsets) ----------------
#define WOFF_VIS  0                       // 2 x 128 (double-buffered vis)
#define WOFF_B1   256
#define WOFF_B2   384
#define WOFF_W3   448
#define WOFF_B3   512                     // 1
#define WOFF_NXT  513                     // 1 (next stolen row)
#define WOFF_RSM  516                     // 16
#define WOFF_THR  532                     // 2 (u64, 8B aligned)
#define WOFF_RED  536                     // 512
#define WOFF_W1H  1048
#define WOFF_W1L  (WOFF_W1H + O1 * SW)
#define WOFF_W2H  (WOFF_W1L + O1 * SW)
#define WOFF_W2L  (WOFF_W2H + O2 * SW)
#define WOFF_DH0  (WOFF_W2L + O2 * SW)    // D buffer 0 (also topk keys x2)
#define WOFF_DH1  (WOFF_DH0 + 128 * SW)   // D buffer 1
#define WTOT      (WOFF_DH1 + 128 * SW)
#define SMEM_TOTAL (WTOT * 4)             // ~178 KB

__device__ __forceinline__ float blockSum512(float v, float* redsm) {
    #pragma unroll
    for (int o = 16; o > 0; o >>= 1) v += __shfl_xor_sync(0xffffffffu, v, o);
    int w = threadIdx.x >> 5;
    __syncthreads();
    if ((threadIdx.x & 31) == 0) redsm[w] = v;
    __syncthreads();
    float s = 0.f;
    #pragma unroll
    for (int q = 0; q < 16; q++) s += redsm[q];
    return s;
}

__global__ void __launch_bounds__(512, 1) mlp_kernel(
    const float* __restrict__ vp,       // [B,N,C]
    const float* __restrict__ epl,      // [B,N,N]
    float* __restrict__ out_ep,         // [B,N,N]
    float* __restrict__ out_ns)         // [B,N,N]
{
    extern __shared__ __align__(16) uint32_t smw[];
    const int tid = threadIdx.x;
    const int lid = tid & 31;
    const int g = lid >> 2;
    const int tg = lid & 3;
    const int wid = tid >> 5;
    const int nq = wid & 3;            // 4 n-groups
    const int mBase = (wid >> 2) * 32; // 4 m-groups x 32 rows

    float* b1s = (float*)(smw + WOFF_B1);
    float* b2s = (float*)(smw + WOFF_B2);
    float* w3s = (float*)(smw + WOFF_W3);
    float* red = (float*)(smw + WOFF_RED);
    float* redsm = (float*)(smw + WOFF_RSM);
    int* nxtp = (int*)(smw + WOFF_NXT);

    const uint32_t smb = smem_u32(smw);

    // ldmatrix per-lane row offsets (words)
    const int laneA = (lid < 16) ? lid * SW : (lid - 16) * SW + 4;
    int laneB;   // {nlo/klo, nlo/khi, nhi/klo, nhi/khi}
    if (lid < 8)       laneB = lid * SW;
    else if (lid < 16) laneB = (lid - 8) * SW + 4;
    else if (lid < 24) laneB = (lid - 8) * SW;
    else               laneB = (lid - 16) * SW + 4;

    const uint32_t aBase0 = smb + (uint32_t)(WOFF_DH0 + mBase * SW + laneA) * 4;
    const uint32_t DBUF_STEP = 128u * SW * 4u;
    const uint32_t b1H0 = smb + (uint32_t)(WOFF_W1H + nq * 32 * SW + laneB) * 4;
    const uint32_t b1L0 = smb + (uint32_t)(WOFF_W1L + nq * 32 * SW + laneB) * 4;
    const uint32_t b2H0 = smb + (uint32_t)(WOFF_W2H + nq * 16 * SW + laneB) * 4;
    const uint32_t b2L0 = smb + (uint32_t)(WOFF_W2L + nq * 16 * SW + laneB) * 4;
    const uint32_t MF_STEP = 16 * SW * 4;
    const uint32_t NT_STEP = 16 * SW * 4;

    // ---- stage weights + scalars ONCE ----
    {
        uint4* d = (uint4*)(smw + WOFF_W1H);
        const uint4* s = (const uint4*)g_w1h;
        for (int q = tid; q < O1 * SW / 4; q += 512) d[q] = s[q];
        d = (uint4*)(smw + WOFF_W1L); s = (const uint4*)g_w1l;
        for (int q = tid; q < O1 * SW / 4; q += 512) d[q] = s[q];
        d = (uint4*)(smw + WOFF_W2H); s = (const uint4*)g_w2h;
        for (int q = tid; q < O2 * SW / 4; q += 512) d[q] = s[q];
        d = (uint4*)(smw + WOFF_W2L); s = (const uint4*)g_w2l;
        for (int q = tid; q < O2 * SW / 4; q += 512) d[q] = s[q];
    }
    if (tid < NC) {
        b1s[tid] = g_b1f[tid];
        ((float*)(smw + WOFF_VIS))[tid] = vp[(size_t)blockIdx.x * NC + tid];
    } else if (tid < NC + O2) {
        int o = tid - NC;
        b2s[o] = g_b2f[o];
        w3s[o] = g_W3f[o];
        if (o == 0) ((float*)(smw + WOFF_B3))[0] = g_b3f;
    }
    __syncthreads();
    const float b3f = ((float*)(smw + WOFF_B3))[0];

    const int jb = tid >> 2;        // D-build: j within tile
    const int chb = tid & 3;        // channel quarter

    int row = blockIdx.x;           // initial static assignment
    int it = 0;
    while (row < NROWS) {
        const int b = row >> 9;
        const int i = row & (NN - 1);
        const int bi = i >> 7;              // first tile index
        const size_t rowbase = (size_t)row * NN;
        float* visb = (float*)(smw + WOFF_VIS) + (it & 1) * 128;

        // steal the NEXT row now; barriers separate this from its readers.
        if (tid == 0) *nxtp = atomicAdd(&g_row_ctr, 1);

        // ---- prologue: build D(bi) + node similarity (direct + mirror) ----
        {
            uint32_t* dn = smw + WOFF_DH0 + (bi & 1) * 128 * SW;
            const int jg0 = bi * 128;
            const float4* v4 =
                (const float4*)(vp + ((size_t)(b * NN + jg0 + jb)) * NC + chb * 32);
            float ns = 0.f;
            #pragma unroll
            for (int q = 0; q < 8; q++) {
                float4 v = v4[q];
                int c = chb * 32 + q * 4;
                float d0 = visb[c] - v.x,     d1 = visb[c + 1] - v.y;
                float d2 = visb[c + 2] - v.z, d3 = visb[c + 3] - v.w;
                float s0 = d0 * d0, s1 = d1 * d1, s2 = d2 * d2, s3 = d3 * d3;
                ns += (s0 + s1) + (s2 + s3);
                int wbase = jb * SW + (c >> 1);
                *(uint2*)&dn[wbase] = make_uint2(pack_h2(s0, s1), pack_h2(s2, s3));
            }
            ns += __shfl_xor_sync(0xffffffffu, ns, 1);
            ns += __shfl_xor_sync(0xffffffffu, ns, 2);
            if (chb == 0) {
                int jg = jg0 + jb;
                out_ns[rowbase + jg] = -ns;
                out_ns[((size_t)(b * NN + jg)) * NN + i] = -ns;  // mirror
            }
        }
        __syncthreads();

        for (int t = bi; t < 4; t++) {
            const int j0 = t * 128;
            const uint32_t aH0 = aBase0 + (uint32_t)(t & 1) * DBUF_STEP;
            uint32_t* dcur = smw + WOFF_DH0 + (t & 1) * 128 * SW;

            // ---- GEMM1: 2-pass fp16 (Ah*Bh + Ah*Bl) ----
            float acc[2][4][4];
            #pragma unroll
            for (int mf = 0; mf < 2; mf++)
                #pragma unroll
                for (int nf = 0; nf < 4; nf++)
                    #pragma unroll
                    for (int q = 0; q < 4; q++) acc[mf][nf][q] = 0.f;

            #pragma unroll
            for (int k = 0; k < 8; k++) {
                uint32_t Ah[2][4], Bh[2][4], Bl[2][4];
                #pragma unroll
                for (int mf = 0; mf < 2; mf++)
                    ldsm4(Ah[mf], aH0 + mf * MF_STEP + k * 32);
                #pragma unroll
                for (int nt = 0; nt < 2; nt++) {
                    ldsm4(Bh[nt], b1H0 + nt * NT_STEP + k * 32);
                    ldsm4(Bl[nt], b1L0 + nt * NT_STEP + k * 32);
                }
                #pragma unroll
                for (int mf = 0; mf < 2; mf++)
                    #pragma unroll
                    for (int nf = 0; nf < 4; nf++) {
                        const uint32_t* bh = &Bh[nf >> 1][(nf & 1) * 2];
                        const uint32_t* bl = &Bl[nf >> 1][(nf & 1) * 2];
                        mma16816(acc[mf][nf], Ah[mf], bh);
                        mma16816(acc[mf][nf], Ah[mf], bl);
                    }
            }
            __syncthreads();   // GEMM1 reads of dcur done; prev logits done

            // ---- epilogue1: bias+leaky -> fp16 H1 (overwrites dcur) ----
            #pragma unroll
            for (int mf = 0; mf < 2; mf++) {
                int r0 = mBase + mf * 16 + g;
                #pragma unroll
                for (int nf = 0; nf < 4; nf++) {
                    int o = nq * 32 + nf * 8 + 2 * tg;
                    float bb0 = b1s[o], bb1 = b1s[o + 1];
                    float x0 = acc[mf][nf][0] + bb0;
                    float x1 = acc[mf][nf][1] + bb1;
                    float x2 = acc[mf][nf][2] + bb0;
                    float x3 = acc[mf][nf][3] + bb1;
                    x0 = (x0 > 0.f) ? x0 : 0.01f * x0;
                    x1 = (x1 > 0.f) ? x1 : 0.01f * x1;
                    x2 = (x2 > 0.f) ? x2 : 0.01f * x2;
                    x3 = (x3 > 0.f) ? x3 : 0.01f * x3;
                    dcur[r0 * SW + (o >> 1)] = pack_h2(x0, x1);
                    dcur[(r0 + 8) * SW + (o >> 1)] = pack_h2(x2, x3);
                }
            }
            __syncthreads();   // H1 ready

            // ---- fused: prefetch | GEMM2 | epi2 | build D(t+1) / vis-next ----
            const float4* v4n = nullptr;
            float4 pre0, pre1, pre2, pre3;
            if (t < 3) {
                v4n = (const float4*)(vp + ((size_t)(b * NN + j0 + 128 + jb)) * NC +
                                      chb * 32);
                pre0 = v4n[0]; pre1 = v4n[1]; pre2 = v4n[2]; pre3 = v4n[3];
            }

            float acc2[2][2][4];
            #pragma unroll
            for (int mf = 0; mf < 2; mf++)
                #pragma unroll
                for (int nf = 0; nf < 2; nf++)
                    #pragma unroll
                    for (int q = 0; q < 4; q++) acc2[mf][nf][q] = 0.f;

            #pragma unroll
            for (int k = 0; k < 8; k++) {
                uint32_t Ah[2][4], Bh[4], Bl[4];
                #pragma unroll
                for (int mf = 0; mf < 2; mf++)
                    ldsm4(Ah[mf], aH0 + mf * MF_STEP + k * 32);
                ldsm4(Bh, b2H0 + k * 32);
                ldsm4(Bl, b2L0 + k * 32);
                #pragma unroll
                for (int mf = 0; mf < 2; mf++)
                    #pragma unroll
                    for (int nf = 0; nf < 2; nf++) {
                        mma16816(acc2[mf][nf], Ah[mf], &Bh[nf * 2]);
                        mma16816(acc2[mf][nf], Ah[mf], &Bl[nf * 2]);
                    }
            }

            // epi2: bias+leaky+W3 dot, cross-lane reduce into red
            {
                float lgA[2] = {0.f, 0.f}, lgB[2] = {0.f, 0.f};
                #pragma unroll
                for (int mf = 0; mf < 2; mf++)
                    #pragma unroll
                    for (int nf = 0; nf < 2; nf++) {
                        int o = nq * 16 + nf * 8 + 2 * tg;
                        float bb0 = b2s[o], bb1 = b2s[o + 1];
                        float w0 = w3s[o], w1v = w3s[o + 1];
                        float x0 = acc2[mf][nf][0] + bb0;
                        float x1 = acc2[mf][nf][1] + bb1;
                        float x2 = acc2[mf][nf][2] + bb0;
                        float x3 = acc2[mf][nf][3] + bb1;
                        x0 = (x0 > 0.f) ? x0 : 0.01f * x0;
                        x1 = (x1 > 0.f) ? x1 : 0.01f * x1;
                        x2 = (x2 > 0.f) ? x2 : 0.01f * x2;
                        x3 = (x3 > 0.f) ? x3 : 0.01f * x3;
                        lgA[mf] = fmaf(x0, w0, lgA[mf]);
                        lgA[mf] = fmaf(x1, w1v, lgA[mf]);
                        lgB[mf] = fmaf(x2, w0, lgB[mf]);
                        lgB[mf] = fmaf(x3, w1v, lgB[mf]);
                    }
                #pragma unroll
                for (int mf = 0; mf < 2; mf++) {
                    float a = lgA[mf], c = lgB[mf];
                    a += __shfl_xor_sync(0xffffffffu, a, 1);
                    a += __shfl_xor_sync(0xffffffffu, a, 2);
                    c += __shfl_xor_sync(0xffffffffu, c, 1);
                    c += __shfl_xor_sync(0xffffffffu, c, 2);
                    if (tg == 0) {
                        int r0 = mBase + mf * 16 + g;
                        red[nq * 128 + r0] = a;
                        red[nq * 128 + r0 + 8] = c;
                    }
                }
            }

            if (t < 3) {
                // build D(t+1) into the other buffer (direct + mirror ns)
                uint32_t* dn = smw + WOFF_DH0 + ((t + 1) & 1) * 128 * SW;
                float ns = 0.f;
                #pragma unroll
                for (int q = 0; q < 8; q++) {
                    float4 v = (q == 0) ? pre0 : (q == 1) ? pre1 :
                               (q == 2) ? pre2 : (q == 3) ? pre3 : v4n[q];
                    int c = chb * 32 + q * 4;
                    float d0 = visb[c] - v.x,     d1 = visb[c + 1] - v.y;
                    float d2 = visb[c + 2] - v.z, d3 = visb[c + 3] - v.w;
                    float s0 = d0 * d0, s1 = d1 * d1, s2 = d2 * d2, s3 = d3 * d3;
                    ns += (s0 + s1) + (s2 + s3);
                    int wbase = jb * SW + (c >> 1);
                    *(uint2*)&dn[wbase] = make_uint2(pack_h2(s0, s1), pack_h2(s2, s3));
                }
                ns += __shfl_xor_sync(0xffffffffu, ns, 1);
                ns += __shfl_xor_sync(0xffffffffu, ns, 2);
                if (chb == 0) {
                    int jg = j0 + 128 + jb;
                    out_ns[rowbase + jg] = -ns;
                    out_ns[((size_t)(b * NN + jg)) * NN + i] = -ns;  // mirror
                }
            } else {
                // last tile: prefetch stolen next row's vis (hidden here)
                int nrow = *nxtp;
                if (nrow < NROWS && tid < 128)
                    ((float*)(smw + WOFF_VIS))[((it + 1) & 1) * 128 + tid] =
                        vp[(size_t)nrow * NC + tid];
            }
            __syncthreads();   // red ready, D(t+1)/vis-next ready

            // logits -> raw sigmoid into g_sg (direct + transposed mirror)
            if (tid < 128) {
                int j = tid;
                float lg = b3f + red[j] + red[128 + j] + red[256 + j] + red[384 + j];
                float sg = 1.f / (1.f + expf(-lg));
                int jg = j0 + j;
                g_sg[rowbase + jg] = sg;
                g_sg[((size_t)(b * NN + jg)) * NN + i] = sg;   // mirror
            }
            // no sync: next GEMM1 reads the other D buffer; the sync after
            // GEMM1 orders this logits block before epi1 overwrites red/dcur.
        }

        row = *nxtp;   // all threads passed the red-ready sync; value stable
        it++;
    }

    // ================= software global barrier =================
    __syncthreads();
    if (tid == 0) {
        __threadfence();
        atomicAdd(&g_bar, 1);
        while (atomicAdd(&g_bar, 0) < GRID) { }
    }
    __syncthreads();
    __threadfence();

    // ================= top-k + normalize (coalesced) =================
    unsigned long long* kbase = (unsigned long long*)(smw + WOFF_DH0);
    unsigned long long* thrp = (unsigned long long*)(smw + WOFF_THR);

    for (int r = blockIdx.x; r < NROWS; r += GRID) {
        const int ir = r & (NN - 1);
        const size_t rb = (size_t)r * NN;

        float el = epl[rb + tid];
        if (tid == ir) el = 0.f;
        float sg = g_sg[rb + tid];
        float v = sg * el;

        float ep_last_sum = blockSum512(el, redsm);

        const unsigned long long mykey =
            ((unsigned long long)__float_as_uint(v) << 32) |
            (unsigned)(NN - 1 - tid);
        unsigned long long key = mykey;

        int pp = 0;
        for (int k = 2; k <= NN; k <<= 1) {
            int j = k >> 1;
            for (; j >= 32; j >>= 1) {
                unsigned long long* kb = kbase + pp * NN;
                kb[tid] = key;
                __syncthreads();
                unsigned long long p = kb[tid ^ j];
                bool keepmin = (((tid & k) == 0) == ((tid & j) == 0));
                key = ((p < key) == keepmin) ? p : key;
                pp ^= 1;
            }
            for (; j > 0; j >>= 1) {
                unsigned long long p = __shfl_xor_sync(0xffffffffu, key, j);
                bool keepmin = (((tid & k) == 0) == ((tid & j) == 0));
                key = ((p < key) == keepmin) ? p : key;
            }
        }
        if (tid == DROPK) *thrp = key;   // sorted ascending
        __syncthreads();
        unsigned long long thr = *thrp;
        float kv = (mykey >= thr) ? v : 0.f;

        float l1 = blockSum512(kv, redsm);
        l1 = fmaxf(l1, 1e-12f);
        float o = kv / l1 * ep_last_sum;
        o += ((tid == ir) ? 1.f : 0.f) + 1e-6f;
        float rs = blockSum512(o, redsm);
        out_ep[rb + tid] = o / rs;
    }
}

extern "C" void kernel_launch(void* const* d_in, const int* in_sizes, int n_in,
                              void* d_out, int out_size) {
    const float* vp  = (const float*)d_in[0];
    const float* epl = (const float*)d_in[1];
    const float* W1  = (const float*)d_in[2];
    const float* g1  = (const float*)d_in[3];
    const float* be1 = (const float*)d_in[4];
    const float* m1  = (const float*)d_in[5];
    const float* v1  = (const float*)d_in[6];
    const float* W2  = (const float*)d_in[7];
    const float* g2  = (const float*)d_in[8];
    const float* be2 = (const float*)d_in[9];
    const float* m2  = (const float*)d_in[10];
    const float* v2  = (const float*)d_in[11];
    const float* W3  = (const float*)d_in[12];
    const float* b3  = (const float*)d_in[13];

    float* out_ep = (float*)d_out;
    float* out_ns = (float*)d_out + NB * NN * NN;

    cudaFuncSetAttribute(mlp_kernel, cudaFuncAttributeMaxDynamicSharedMemorySize,
                         SMEM_TOTAL);

    prelude_kernel<<<32, 256>>>(W1, g1, be1, m1, v1, W2, g2, be2, m2, v2, W3, b3);
    mlp_kernel<<<GRID, 512, SMEM_TOTAL>>>(vp, epl, out_ep, out_ns);
}

// round 15
// speedup vs baseline: 1.0341x; 1.0341x over previous
#include <cuda_runtime.h>
#include <cuda_fp16.h>
#include <math.h>
#include <stdint.h>

#define NB 2
#define NN 512
#define NC 128
#define O1 128
#define O2 64
#define DROPK 52         // 512 - 460
#define SW 68            // row stride in u32 words (136 fp16; ldmatrix conflict-free)
#define NROWS (NB * NN)
#define GRID 148

__device__ __forceinline__ uint32_t smem_u32(const void* p) {
    uint32_t a;
    asm("{ .reg .u64 t; cvta.to.shared.u64 t, %1; cvt.u32.u64 %0, t; }"
        : "=r"(a) : "l"(p));
    return a;
}

// pack two fp32 into fp16x2 (lo = x0, hi = x1)
__device__ __forceinline__ uint32_t pack_h2(float x0, float x1) {
    uint32_t r;
    asm("cvt.rn.f16x2.f32 %0, %1, %2;" : "=r"(r) : "f"(x1), "f"(x0));
    return r;
}
// pack + residual (for weights)
__device__ __forceinline__ void split2h(float x0, float x1, uint32_t& hp, uint32_t& lp) {
    hp = pack_h2(x0, x1);
    __half2 hb = *reinterpret_cast<__half2*>(&hp);
    float l0 = x0 - __half2float(hb.x);
    float l1 = x1 - __half2float(hb.y);
    lp = pack_h2(l0, l1);
}

__device__ __forceinline__ void mma16816(float* c, const uint32_t* a, const uint32_t* b) {
    asm volatile(
        "mma.sync.aligned.m16n8k16.row.col.f32.f16.f16.f32 "
        "{%0,%1,%2,%3}, {%4,%5,%6,%7}, {%8,%9}, {%0,%1,%2,%3};"
        : "+f"(c[0]), "+f"(c[1]), "+f"(c[2]), "+f"(c[3])
        : "r"(a[0]), "r"(a[1]), "r"(a[2]), "r"(a[3]), "r"(b[0]), "r"(b[1]));
}

__device__ __forceinline__ void ldsm4(uint32_t* r, uint32_t saddr) {
    asm volatile("ldmatrix.sync.aligned.m8n8.x4.shared.b16 {%0,%1,%2,%3}, [%4];"
                 : "=r"(r[0]), "=r"(r[1]), "=r"(r[2]), "=r"(r[3]) : "r"(saddr));
}

// ---------------- folded + packed weights (prelude output) ----------------
__device__ uint32_t g_w1h[O1 * SW];
__device__ uint32_t g_w1l[O1 * SW];
__device__ uint32_t g_w2h[O2 * SW];
__device__ uint32_t g_w2l[O2 * SW];
__device__ float g_b1f[O1];
__device__ float g_b2f[O2];
__device__ float g_W3f[O2];
__device__ float g_b3f;
__device__ int g_row_ctr;       // work-stealing counter (reset by prelude)
// raw sigmoid(logits); fully populated (direct + transposed mirror writes).
__device__ float g_sg[(size_t)NB * NN * NN];

__global__ void prelude_kernel(
    const float* __restrict__ W1, const float* __restrict__ g1,
    const float* __restrict__ be1, const float* __restrict__ m1,
    const float* __restrict__ v1,
    const float* __restrict__ W2, const float* __restrict__ g2,
    const float* __restrict__ be2, const float* __restrict__ m2,
    const float* __restrict__ v2,
    const float* __restrict__ W3, const float* __restrict__ b3)
{
    __shared__ float s1[O1], s2[O2];
    int t = threadIdx.x;
    if (t < O1) {
        float s = g1[t] / sqrtf(v1[t] + 1e-5f);
        s1[t] = s;
        if (blockIdx.x == 0) g_b1f[t] = be1[t] - m1[t] * s;
    } else if (t < O1 + O2) {
        int o = t - O1;
        float s = g2[o] / sqrtf(v2[o] + 1e-5f);
        s2[o] = s;
        if (blockIdx.x == 0) g_b2f[o] = be2[o] - m2[o] * s;
    } else if (t < O1 + 2 * O2) {
        int o = t - (O1 + O2);
        if (blockIdx.x == 0) {
            g_W3f[o] = W3[o];
            if (o == 0) { g_b3f = b3[0]; g_row_ctr = GRID; }
        }
    }
    __syncthreads();
    int stride = blockDim.x * gridDim.x;
    int base = blockIdx.x * blockDim.x + t;
    for (int idx = base; idx < O1 * 64; idx += stride) {
        int o = idx >> 6, cp = idx & 63;
        float v0 = W1[o * NC + 2 * cp] * s1[o];
        float v1v = W1[o * NC + 2 * cp + 1] * s1[o];
        uint32_t hp, lp;
        split2h(v0, v1v, hp, lp);
        g_w1h[o * SW + cp] = hp;
        g_w1l[o * SW + cp] = lp;
    }
    for (int idx = base; idx < O2 * 64; idx += stride) {
        int n = idx >> 6, cp = idx & 63;
        float v0 = W2[n * O1 + 2 * cp] * s2[n];
        float v1v = W2[n * O1 + 2 * cp + 1] * s2[n];
        uint32_t hp, lp;
        split2h(v0, v1v, hp, lp);
        g_w2h[n * SW + cp] = hp;
        g_w2l[n * SW + cp] = lp;
    }
}

// ---------------- SMEM layout (u32 word offsets) ----------------
#define WOFF_VIS  0                       // 2 x 128 (double-buffered vis)
#define WOFF_B1   256
#define WOFF_B2   384
#define WOFF_W3   448
#define WOFF_B3   512                     // 1
#define WOFF_NXT  513                     // 1 (next stolen row)
#define WOFF_RED  516                     // 512
#define WOFF_W1H  1028
#define WOFF_W1L  (WOFF_W1H + O1 * SW)
#define WOFF_W2H  (WOFF_W1L + O1 * SW)
#define WOFF_W2L  (WOFF_W2H + O2 * SW)
#define WOFF_DH0  (WOFF_W2L + O2 * SW)    // D buffer 0
#define WOFF_DH1  (WOFF_DH0 + 128 * SW)   // D buffer 1
#define WTOT      (WOFF_DH1 + 128 * SW)
#define SMEM_TOTAL (WTOT * 4)             // ~178 KB

__global__ void __launch_bounds__(512, 1) mlp_kernel(
    const float* __restrict__ vp,       // [B,N,C]
    float* __restrict__ out_ns)         // [B,N,N] (direct + mirror writes)
{
    extern __shared__ __align__(16) uint32_t smw[];
    const int tid = threadIdx.x;
    const int lid = tid & 31;
    const int g = lid >> 2;
    const int tg = lid & 3;
    const int wid = tid >> 5;
    const int nq = wid & 3;            // 4 n-groups
    const int mBase = (wid >> 2) * 32; // 4 m-groups x 32 rows

    float* b1s = (float*)(smw + WOFF_B1);
    float* b2s = (float*)(smw + WOFF_B2);
    float* w3s = (float*)(smw + WOFF_W3);
    float* red = (float*)(smw + WOFF_RED);
    int* nxtp = (int*)(smw + WOFF_NXT);

    const uint32_t smb = smem_u32(smw);

    // ldmatrix per-lane row offsets (words)
    const int laneA = (lid < 16) ? lid * SW : (lid - 16) * SW + 4;
    int laneB;   // {nlo/klo, nlo/khi, nhi/klo, nhi/khi}
    if (lid < 8)       laneB = lid * SW;
    else if (lid < 16) laneB = (lid - 8) * SW + 4;
    else if (lid < 24) laneB = (lid - 8) * SW;
    else               laneB = (lid - 16) * SW + 4;

    const uint32_t aBase0 = smb + (uint32_t)(WOFF_DH0 + mBase * SW + laneA) * 4;
    const uint32_t DBUF_STEP = 128u * SW * 4u;
    const uint32_t b1H0 = smb + (uint32_t)(WOFF_W1H + nq * 32 * SW + laneB) * 4;
    const uint32_t b1L0 = smb + (uint32_t)(WOFF_W1L + nq * 32 * SW + laneB) * 4;
    const uint32_t b2H0 = smb + (uint32_t)(WOFF_W2H + nq * 16 * SW + laneB) * 4;
    const uint32_t b2L0 = smb + (uint32_t)(WOFF_W2L + nq * 16 * SW + laneB) * 4;
    const uint32_t MF_STEP = 16 * SW * 4;
    const uint32_t NT_STEP = 16 * SW * 4;

    // ---- stage weights + scalars ONCE ----
    {
        uint4* d = (uint4*)(smw + WOFF_W1H);
        const uint4* s = (const uint4*)g_w1h;
        for (int q = tid; q < O1 * SW / 4; q += 512) d[q] = s[q];
        d = (uint4*)(smw + WOFF_W1L); s = (const uint4*)g_w1l;
        for (int q = tid; q < O1 * SW / 4; q += 512) d[q] = s[q];
        d = (uint4*)(smw + WOFF_W2H); s = (const uint4*)g_w2h;
        for (int q = tid; q < O2 * SW / 4; q += 512) d[q] = s[q];
        d = (uint4*)(smw + WOFF_W2L); s = (const uint4*)g_w2l;
        for (int q = tid; q < O2 * SW / 4; q += 512) d[q] = s[q];
    }
    if (tid < NC) {
        b1s[tid] = g_b1f[tid];
        ((float*)(smw + WOFF_VIS))[tid] = vp[(size_t)blockIdx.x * NC + tid];
    } else if (tid < NC + O2) {
        int o = tid - NC;
        b2s[o] = g_b2f[o];
        w3s[o] = g_W3f[o];
        if (o == 0) ((float*)(smw + WOFF_B3))[0] = g_b3f;
    }
    __syncthreads();
    const float b3f = ((float*)(smw + WOFF_B3))[0];

    const int jb = tid >> 2;        // D-build: j within tile
    const int chb = tid & 3;        // channel quarter

    int row = blockIdx.x;           // initial static assignment
    int it = 0;
    while (row < NROWS) {
        const int b = row >> 9;
        const int i = row & (NN - 1);
        const int bi = i >> 7;              // first tile index
        const size_t rowbase = (size_t)row * NN;
        float* visb = (float*)(smw + WOFF_VIS) + (it & 1) * 128;

        // steal the NEXT row now; barriers separate this from its readers.
        if (tid == 0) *nxtp = atomicAdd(&g_row_ctr, 1);

        // ---- prologue: build D(bi) + node similarity (direct + mirror) ----
        {
            uint32_t* dn = smw + WOFF_DH0 + (bi & 1) * 128 * SW;
            const int jg0 = bi * 128;
            const float4* v4 =
                (const float4*)(vp + ((size_t)(b * NN + jg0 + jb)) * NC + chb * 32);
            float ns = 0.f;
            #pragma unroll
            for (int q = 0; q < 8; q++) {
                float4 v = v4[q];
                int c = chb * 32 + q * 4;
                float d0 = visb[c] - v.x,     d1 = visb[c + 1] - v.y;
                float d2 = visb[c + 2] - v.z, d3 = visb[c + 3] - v.w;
                float s0 = d0 * d0, s1 = d1 * d1, s2 = d2 * d2, s3 = d3 * d3;
                ns += (s0 + s1) + (s2 + s3);
                int wbase = jb * SW + (c >> 1);
                *(uint2*)&dn[wbase] = make_uint2(pack_h2(s0, s1), pack_h2(s2, s3));
            }
            ns += __shfl_xor_sync(0xffffffffu, ns, 1);
            ns += __shfl_xor_sync(0xffffffffu, ns, 2);
            if (chb == 0) {
                int jg = jg0 + jb;
                out_ns[rowbase + jg] = -ns;
                out_ns[((size_t)(b * NN + jg)) * NN + i] = -ns;  // mirror
            }
        }
        __syncthreads();

        for (int t = bi; t < 4; t++) {
            const int j0 = t * 128;
            const uint32_t aH0 = aBase0 + (uint32_t)(t & 1) * DBUF_STEP;
            uint32_t* dcur = smw + WOFF_DH0 + (t & 1) * 128 * SW;

            // ---- GEMM1: 2-pass fp16 (Ah*Bh + Ah*Bl) ----
            float acc[2][4][4];
            #pragma unroll
            for (int mf = 0; mf < 2; mf++)
                #pragma unroll
                for (int nf = 0; nf < 4; nf++)
                    #pragma unroll
                    for (int q = 0; q < 4; q++) acc[mf][nf][q] = 0.f;

            #pragma unroll
            for (int k = 0; k < 8; k++) {
                uint32_t Ah[2][4], Bh[2][4], Bl[2][4];
                #pragma unroll
                for (int mf = 0; mf < 2; mf++)
                    ldsm4(Ah[mf], aH0 + mf * MF_STEP + k * 32);
                #pragma unroll
                for (int nt = 0; nt < 2; nt++) {
                    ldsm4(Bh[nt], b1H0 + nt * NT_STEP + k * 32);
                    ldsm4(Bl[nt], b1L0 + nt * NT_STEP + k * 32);
                }
                #pragma unroll
                for (int mf = 0; mf < 2; mf++)
                    #pragma unroll
                    for (int nf = 0; nf < 4; nf++) {
                        const uint32_t* bh = &Bh[nf >> 1][(nf & 1) * 2];
                        const uint32_t* bl = &Bl[nf >> 1][(nf & 1) * 2];
                        mma16816(acc[mf][nf], Ah[mf], bh);
                        mma16816(acc[mf][nf], Ah[mf], bl);
                    }
            }
            __syncthreads();   // GEMM1 reads of dcur done; prev logits done

            // ---- epilogue1: bias+leaky -> fp16 H1 (overwrites dcur) ----
            #pragma unroll
            for (int mf = 0; mf < 2; mf++) {
                int r0 = mBase + mf * 16 + g;
                #pragma unroll
                for (int nf = 0; nf < 4; nf++) {
                    int o = nq * 32 + nf * 8 + 2 * tg;
                    float bb0 = b1s[o], bb1 = b1s[o + 1];
                    float x0 = acc[mf][nf][0] + bb0;
                    float x1 = acc[mf][nf][1] + bb1;
                    float x2 = acc[mf][nf][2] + bb0;
                    float x3 = acc[mf][nf][3] + bb1;
                    x0 = (x0 > 0.f) ? x0 : 0.01f * x0;
                    x1 = (x1 > 0.f) ? x1 : 0.01f * x1;
                    x2 = (x2 > 0.f) ? x2 : 0.01f * x2;
                    x3 = (x3 > 0.f) ? x3 : 0.01f * x3;
                    dcur[r0 * SW + (o >> 1)] = pack_h2(x0, x1);
                    dcur[(r0 + 8) * SW + (o >> 1)] = pack_h2(x2, x3);
                }
            }
            __syncthreads();   // H1 ready

            // ---- fused: prefetch | GEMM2 | epi2 | build D(t+1) / vis-next ----
            const float4* v4n = nullptr;
            float4 pre0, pre1, pre2, pre3;
            if (t < 3) {
                v4n = (const float4*)(vp + ((size_t)(b * NN + j0 + 128 + jb)) * NC +
                                      chb * 32);
                pre0 = v4n[0]; pre1 = v4n[1]; pre2 = v4n[2]; pre3 = v4n[3];
            }

            float acc2[2][2][4];
            #pragma unroll
            for (int mf = 0; mf < 2; mf++)
                #pragma unroll
                for (int nf = 0; nf < 2; nf++)
                    #pragma unroll
                    for (int q = 0; q < 4; q++) acc2[mf][nf][q] = 0.f;

            #pragma unroll
            for (int k = 0; k < 8; k++) {
                uint32_t Ah[2][4], Bh[4], Bl[4];
                #pragma unroll
                for (int mf = 0; mf < 2; mf++)
                    ldsm4(Ah[mf], aH0 + mf * MF_STEP + k * 32);
                ldsm4(Bh, b2H0 + k * 32);
                ldsm4(Bl, b2L0 + k * 32);
                #pragma unroll
                for (int mf = 0; mf < 2; mf++)
                    #pragma unroll
                    for (int nf = 0; nf < 2; nf++) {
                        mma16816(acc2[mf][nf], Ah[mf], &Bh[nf * 2]);
                        mma16816(acc2[mf][nf], Ah[mf], &Bl[nf * 2]);
                    }
            }

            // epi2: bias+leaky+W3 dot, cross-lane reduce into red
            {
                float lgA[2] = {0.f, 0.f}, lgB[2] = {0.f, 0.f};
                #pragma unroll
                for (int mf = 0; mf < 2; mf++)
                    #pragma unroll
                    for (int nf = 0; nf < 2; nf++) {
                        int o = nq * 16 + nf * 8 + 2 * tg;
                        float bb0 = b2s[o], bb1 = b2s[o + 1];
                        float w0 = w3s[o], w1v = w3s[o + 1];
                        float x0 = acc2[mf][nf][0] + bb0;
                        float x1 = acc2[mf][nf][1] + bb1;
                        float x2 = acc2[mf][nf][2] + bb0;
                        float x3 = acc2[mf][nf][3] + bb1;
                        x0 = (x0 > 0.f) ? x0 : 0.01f * x0;
                        x1 = (x1 > 0.f) ? x1 : 0.01f * x1;
                        x2 = (x2 > 0.f) ? x2 : 0.01f * x2;
                        x3 = (x3 > 0.f) ? x3 : 0.01f * x3;
                        lgA[mf] = fmaf(x0, w0, lgA[mf]);
                        lgA[mf] = fmaf(x1, w1v, lgA[mf]);
                        lgB[mf] = fmaf(x2, w0, lgB[mf]);
                        lgB[mf] = fmaf(x3, w1v, lgB[mf]);
                    }
                #pragma unroll
                for (int mf = 0; mf < 2; mf++) {
                    float a = lgA[mf], c = lgB[mf];
                    a += __shfl_xor_sync(0xffffffffu, a, 1);
                    a += __shfl_xor_sync(0xffffffffu, a, 2);
                    c += __shfl_xor_sync(0xffffffffu, c, 1);
                    c += __shfl_xor_sync(0xffffffffu, c, 2);
                    if (tg == 0) {
                        int r0 = mBase + mf * 16 + g;
                        red[nq * 128 + r0] = a;
                        red[nq * 128 + r0 + 8] = c;
                    }
                }
            }

            if (t < 3) {
                // build D(t+1) into the other buffer (direct + mirror ns)
                uint32_t* dn = smw + WOFF_DH0 + ((t + 1) & 1) * 128 * SW;
                float ns = 0.f;
                #pragma unroll
                for (int q = 0; q < 8; q++) {
                    float4 v = (q == 0) ? pre0 : (q == 1) ? pre1 :
                               (q == 2) ? pre2 : (q == 3) ? pre3 : v4n[q];
                    int c = chb * 32 + q * 4;
                    float d0 = visb[c] - v.x,     d1 = visb[c + 1] - v.y;
                    float d2 = visb[c + 2] - v.z, d3 = visb[c + 3] - v.w;
                    float s0 = d0 * d0, s1 = d1 * d1, s2 = d2 * d2, s3 = d3 * d3;
                    ns += (s0 + s1) + (s2 + s3);
                    int wbase = jb * SW + (c >> 1);
                    *(uint2*)&dn[wbase] = make_uint2(pack_h2(s0, s1), pack_h2(s2, s3));
                }
                ns += __shfl_xor_sync(0xffffffffu, ns, 1);
                ns += __shfl_xor_sync(0xffffffffu, ns, 2);
                if (chb == 0) {
                    int jg = j0 + 128 + jb;
                    out_ns[rowbase + jg] = -ns;
                    out_ns[((size_t)(b * NN + jg)) * NN + i] = -ns;  // mirror
                }
            } else {
                // last tile: prefetch stolen next row's vis (hidden here)
                int nrow = *nxtp;
                if (nrow < NROWS && tid < 128)
                    ((float*)(smw + WOFF_VIS))[((it + 1) & 1) * 128 + tid] =
                        vp[(size_t)nrow * NC + tid];
            }
            __syncthreads();   // red ready, D(t+1)/vis-next ready

            // logits -> raw sigmoid into g_sg (direct + transposed mirror)
            if (tid < 128) {
                int j = tid;
                float lg = b3f + red[j] + red[128 + j] + red[256 + j] + red[384 + j];
                float sg = 1.f / (1.f + expf(-lg));
                int jg = j0 + j;
                g_sg[rowbase + jg] = sg;
                g_sg[((size_t)(b * NN + jg)) * NN + i] = sg;   // mirror
            }
            // no sync: next GEMM1 reads the other D buffer; the sync after
            // GEMM1 orders this logits block before epi1 overwrites red/dcur.
        }

        row = *nxtp;   // all threads passed the red-ready sync; value stable
        it++;
    }
}

// ---------------- top-k + normalize (fully coalesced) ----------------
__device__ __forceinline__ float blockSum512(float v, float* redsm) {
    #pragma unroll
    for (int o = 16; o > 0; o >>= 1) v += __shfl_xor_sync(0xffffffffu, v, o);
    int w = threadIdx.x >> 5;
    __syncthreads();
    if ((threadIdx.x & 31) == 0) redsm[w] = v;
    __syncthreads();
    float s = 0.f;
    #pragma unroll
    for (int q = 0; q < 16; q++) s += redsm[q];
    return s;
}

__global__ void __launch_bounds__(512) topk_kernel(
    const float* __restrict__ epl,
    float* __restrict__ out_ep)
{
    __shared__ unsigned long long keys[2 * NN];
    __shared__ float redsm[16];
    __shared__ unsigned long long thr_s;

    const int row = blockIdx.x;
    const int i = row & (NN - 1);
    const int tid = threadIdx.x;
    const size_t rowbase = (size_t)row * NN;

    float el = epl[rowbase + tid];
    if (tid == i) el = 0.f;
    float sg = g_sg[rowbase + tid];
    float v = sg * el;

    float ep_last_sum = blockSum512(el, redsm);

    const unsigned long long mykey =
        ((unsigned long long)__float_as_uint(v) << 32) | (unsigned)(NN - 1 - tid);
    unsigned long long key = mykey;

    int pp = 0;
    for (int k = 2; k <= NN; k <<= 1) {
        int j = k >> 1;
        for (; j >= 32; j >>= 1) {
            unsigned long long* kb = keys + pp * NN;
            kb[tid] = key;
            __syncthreads();
            unsigned long long p = kb[tid ^ j];
            bool keepmin = (((tid & k) == 0) == ((tid & j) == 0));
            key = ((p < key) == keepmin) ? p : key;
            pp ^= 1;
        }
        for (; j > 0; j >>= 1) {
            unsigned long long p = __shfl_xor_sync(0xffffffffu, key, j);
            bool keepmin = (((tid & k) == 0) == ((tid & j) == 0));
            key = ((p < key) == keepmin) ? p : key;
        }
    }
    if (tid == DROPK) thr_s = key;   // sorted ascending: 52nd smallest
    __syncthreads();
    unsigned long long thr = thr_s;
    float kv = (mykey >= thr) ? v : 0.f;

    float l1 = blockSum512(kv, redsm);
    l1 = fmaxf(l1, 1e-12f);
    float o = kv / l1 * ep_last_sum;
    o += ((tid == i) ? 1.f : 0.f) + 1e-6f;
    float rs = blockSum512(o, redsm);
    out_ep[rowbase + tid] = o / rs;
}

extern "C" void kernel_launch(void* const* d_in, const int* in_sizes, int n_in,
                              void* d_out, int out_size) {
    const float* vp  = (const float*)d_in[0];
    const float* epl = (const float*)d_in[1];
    const float* W1  = (const float*)d_in[2];
    const float* g1  = (const float*)d_in[3];
    const float* be1 = (const float*)d_in[4];
    const float* m1  = (const float*)d_in[5];
    const float* v1  = (const float*)d_in[6];
    const float* W2  = (const float*)d_in[7];
    const float* g2  = (const float*)d_in[8];
    const float* be2 = (const float*)d_in[9];
    const float* m2  = (const float*)d_in[10];
    const float* v2  = (const float*)d_in[11];
    const float* W3  = (const float*)d_in[12];
    const float* b3  = (const float*)d_in[13];

    float* out_ep = (float*)d_out;
    float* out_ns = (float*)d_out + NB * NN * NN;

    cudaFuncSetAttribute(mlp_kernel, cudaFuncAttributeMaxDynamicSharedMemorySize,
                         SMEM_TOTAL);

    prelude_kernel<<<32, 256>>>(W1, g1, be1, m1, v1, W2, g2, be2, m2, v2, W3, b3);
    mlp_kernel<<<GRID, 512, SMEM_TOTAL>>>(vp, out_ns);
    topk_kernel<<<NROWS, 512>>>(epl, out_ep);
}

// round 16
// speedup vs baseline: 1.0349x; 1.0008x over previous
#include <cuda_runtime.h>
#include <cuda_fp16.h>
#include <math.h>
#include <stdint.h>

#define NB 2
#define NN 512
#define NC 128
#define O1 128
#define O2 64
#define DROPK 52         // 512 - 460
#define SW 68            // row stride in u32 words (136 fp16; ldmatrix conflict-free)
#define NROWS (NB * NN)
#define GRID 148

__device__ __forceinline__ uint32_t smem_u32(const void* p) {
    uint32_t a;
    asm("{ .reg .u64 t; cvta.to.shared.u64 t, %1; cvt.u32.u64 %0, t; }"
        : "=r"(a) : "l"(p));
    return a;
}

// pack two fp32 into fp16x2 (lo = x0, hi = x1)
__device__ __forceinline__ uint32_t pack_h2(float x0, float x1) {
    uint32_t r;
    asm("cvt.rn.f16x2.f32 %0, %1, %2;" : "=r"(r) : "f"(x1), "f"(x0));
    return r;
}
// pack + residual (for weights)
__device__ __forceinline__ void split2h(float x0, float x1, uint32_t& hp, uint32_t& lp) {
    hp = pack_h2(x0, x1);
    __half2 hb = *reinterpret_cast<__half2*>(&hp);
    float l0 = x0 - __half2float(hb.x);
    float l1 = x1 - __half2float(hb.y);
    lp = pack_h2(l0, l1);
}

__device__ __forceinline__ void mma16816(float* c, const uint32_t* a, const uint32_t* b) {
    asm volatile(
        "mma.sync.aligned.m16n8k16.row.col.f32.f16.f16.f32 "
        "{%0,%1,%2,%3}, {%4,%5,%6,%7}, {%8,%9}, {%0,%1,%2,%3};"
        : "+f"(c[0]), "+f"(c[1]), "+f"(c[2]), "+f"(c[3])
        : "r"(a[0]), "r"(a[1]), "r"(a[2]), "r"(a[3]), "r"(b[0]), "r"(b[1]));
}

__device__ __forceinline__ void ldsm4(uint32_t* r, uint32_t saddr) {
    asm volatile("ldmatrix.sync.aligned.m8n8.x4.shared.b16 {%0,%1,%2,%3}, [%4];"
                 : "=r"(r[0]), "=r"(r[1]), "=r"(r[2]), "=r"(r[3]) : "r"(saddr));
}

// ---------------- device state ----------------
__device__ int g_row_ctr = GRID;   // work-steal counter (self-resetting)
__device__ int g_done = 0;         // completion counter (self-resetting)
// raw sigmoid(logits); fully populated (direct + transposed mirror writes).
__device__ float g_sg[(size_t)NB * NN * NN];

// ---------------- SMEM layout (u32 word offsets) ----------------
#define WOFF_VIS  0                       // 2 x 128 (double-buffered vis)
#define WOFF_B1   256
#define WOFF_B2   384
#define WOFF_W3   448
#define WOFF_B3   512                     // 1
#define WOFF_NXT  513                     // 1 (next stolen row)
#define WOFF_RED  516                     // 512 (also scratch for s1/s2)
#define WOFF_W1H  1028
#define WOFF_W1L  (WOFF_W1H + O1 * SW)
#define WOFF_W2H  (WOFF_W1L + O1 * SW)
#define WOFF_W2L  (WOFF_W2H + O2 * SW)
#define WOFF_DH0  (WOFF_W2L + O2 * SW)    // D buffer 0
#define WOFF_DH1  (WOFF_DH0 + 128 * SW)   // D buffer 1
#define WTOT      (WOFF_DH1 + 128 * SW)
#define SMEM_TOTAL (WTOT * 4)             // ~178 KB

__global__ void __launch_bounds__(512, 1) mlp_kernel(
    const float* __restrict__ vp,       // [B,N,C]
    const float* __restrict__ W1, const float* __restrict__ g1,
    const float* __restrict__ be1, const float* __restrict__ m1,
    const float* __restrict__ v1,
    const float* __restrict__ W2, const float* __restrict__ g2,
    const float* __restrict__ be2, const float* __restrict__ m2,
    const float* __restrict__ v2,
    const float* __restrict__ W3, const float* __restrict__ b3,
    float* __restrict__ out_ns)         // [B,N,N] (direct + mirror writes)
{
    extern __shared__ __align__(16) uint32_t smw[];
    const int tid = threadIdx.x;
    const int lid = tid & 31;
    const int g = lid >> 2;
    const int tg = lid & 3;
    const int wid = tid >> 5;
    const int nq = wid & 3;            // 4 n-groups
    const int mBase = (wid >> 2) * 32; // 4 m-groups x 32 rows

    float* b1s = (float*)(smw + WOFF_B1);
    float* b2s = (float*)(smw + WOFF_B2);
    float* w3s = (float*)(smw + WOFF_W3);
    float* red = (float*)(smw + WOFF_RED);
    int* nxtp = (int*)(smw + WOFF_NXT);

    const uint32_t smb = smem_u32(smw);

    // ldmatrix per-lane row offsets (words)
    const int laneA = (lid < 16) ? lid * SW : (lid - 16) * SW + 4;
    int laneB;   // {nlo/klo, nlo/khi, nhi/klo, nhi/khi}
    if (lid < 8)       laneB = lid * SW;
    else if (lid < 16) laneB = (lid - 8) * SW + 4;
    else if (lid < 24) laneB = (lid - 8) * SW;
    else               laneB = (lid - 16) * SW + 4;

    const uint32_t aBase0 = smb + (uint32_t)(WOFF_DH0 + mBase * SW + laneA) * 4;
    const uint32_t DBUF_STEP = 128u * SW * 4u;
    const uint32_t b1H0 = smb + (uint32_t)(WOFF_W1H + nq * 32 * SW + laneB) * 4;
    const uint32_t b1L0 = smb + (uint32_t)(WOFF_W1L + nq * 32 * SW + laneB) * 4;
    const uint32_t b2H0 = smb + (uint32_t)(WOFF_W2H + nq * 16 * SW + laneB) * 4;
    const uint32_t b2L0 = smb + (uint32_t)(WOFF_W2L + nq * 16 * SW + laneB) * 4;
    const uint32_t MF_STEP = 16 * SW * 4;
    const uint32_t NT_STEP = 16 * SW * 4;

    // ---- prologue phase 1: scales, biases, first-row vis ----
    if (tid < NC) {
        float s = g1[tid] / sqrtf(v1[tid] + 1e-5f);
        red[tid] = s;                      // s1
        b1s[tid] = be1[tid] - m1[tid] * s;
        ((float*)(smw + WOFF_VIS))[tid] = vp[(size_t)blockIdx.x * NC + tid];
    } else if (tid < NC + O2) {
        int o = tid - NC;
        float s = g2[o] / sqrtf(v2[o] + 1e-5f);
        red[O1 + o] = s;                   // s2
        b2s[o] = be2[o] - m2[o] * s;
        w3s[o] = W3[o];
        if (o == 0) ((float*)(smw + WOFF_B3))[0] = b3[0];
    }
    __syncthreads();

    // ---- prologue phase 2: fold + split weights directly into smem ----
    for (int idx = tid; idx < O1 * 64; idx += 512) {
        int o = idx >> 6, cp = idx & 63;
        float2 w = *(const float2*)&W1[o * NC + 2 * cp];
        float s = red[o];
        uint32_t hp, lp;
        split2h(w.x * s, w.y * s, hp, lp);
        smw[WOFF_W1H + o * SW + cp] = hp;
        smw[WOFF_W1L + o * SW + cp] = lp;
    }
    for (int idx = tid; idx < O2 * 64; idx += 512) {
        int n = idx >> 6, cp = idx & 63;
        float2 w = *(const float2*)&W2[n * O1 + 2 * cp];
        float s = red[O1 + n];
        uint32_t hp, lp;
        split2h(w.x * s, w.y * s, hp, lp);
        smw[WOFF_W2H + n * SW + cp] = hp;
        smw[WOFF_W2L + n * SW + cp] = lp;
    }
    __syncthreads();
    const float b3f = ((float*)(smw + WOFF_B3))[0];

    const int jb = tid >> 2;        // D-build: j within tile
    const int chb = tid & 3;        // channel quarter

    int row = blockIdx.x;           // initial static assignment
    int it = 0;
    while (row < NROWS) {
        const int b = row >> 9;
        const int i = row & (NN - 1);
        const int bi = i >> 7;              // first tile index
        const size_t rowbase = (size_t)row * NN;
        float* visb = (float*)(smw + WOFF_VIS) + (it & 1) * 128;

        // steal the NEXT row now; barriers separate this from its readers.
        if (tid == 0) *nxtp = atomicAdd(&g_row_ctr, 1);

        // ---- prologue: build D(bi) + node similarity (direct + mirror) ----
        {
            uint32_t* dn = smw + WOFF_DH0 + (bi & 1) * 128 * SW;
            const int jg0 = bi * 128;
            const float4* v4 =
                (const float4*)(vp + ((size_t)(b * NN + jg0 + jb)) * NC + chb * 32);
            float ns = 0.f;
            #pragma unroll
            for (int q = 0; q < 8; q++) {
                float4 v = v4[q];
                int c = chb * 32 + q * 4;
                float d0 = visb[c] - v.x,     d1 = visb[c + 1] - v.y;
                float d2 = visb[c + 2] - v.z, d3 = visb[c + 3] - v.w;
                float s0 = d0 * d0, s1 = d1 * d1, s2 = d2 * d2, s3 = d3 * d3;
                ns += (s0 + s1) + (s2 + s3);
                int wbase = jb * SW + (c >> 1);
                *(uint2*)&dn[wbase] = make_uint2(pack_h2(s0, s1), pack_h2(s2, s3));
            }
            ns += __shfl_xor_sync(0xffffffffu, ns, 1);
            ns += __shfl_xor_sync(0xffffffffu, ns, 2);
            if (chb == 0) {
                int jg = jg0 + jb;
                out_ns[rowbase + jg] = -ns;
                out_ns[((size_t)(b * NN + jg)) * NN + i] = -ns;  // mirror
            }
        }
        __syncthreads();

        for (int t = bi; t < 4; t++) {
            const int j0 = t * 128;
            const uint32_t aH0 = aBase0 + (uint32_t)(t & 1) * DBUF_STEP;
            uint32_t* dcur = smw + WOFF_DH0 + (t & 1) * 128 * SW;

            // ---- GEMM1: 2-pass fp16 (Ah*Bh + Ah*Bl) ----
            float acc[2][4][4];
            #pragma unroll
            for (int mf = 0; mf < 2; mf++)
                #pragma unroll
                for (int nf = 0; nf < 4; nf++)
                    #pragma unroll
                    for (int q = 0; q < 4; q++) acc[mf][nf][q] = 0.f;

            #pragma unroll
            for (int k = 0; k < 8; k++) {
                uint32_t Ah[2][4], Bh[2][4], Bl[2][4];
                #pragma unroll
                for (int mf = 0; mf < 2; mf++)
                    ldsm4(Ah[mf], aH0 + mf * MF_STEP + k * 32);
                #pragma unroll
                for (int nt = 0; nt < 2; nt++) {
                    ldsm4(Bh[nt], b1H0 + nt * NT_STEP + k * 32);
                    ldsm4(Bl[nt], b1L0 + nt * NT_STEP + k * 32);
                }
                #pragma unroll
                for (int mf = 0; mf < 2; mf++)
                    #pragma unroll
                    for (int nf = 0; nf < 4; nf++) {
                        const uint32_t* bh = &Bh[nf >> 1][(nf & 1) * 2];
                        const uint32_t* bl = &Bl[nf >> 1][(nf & 1) * 2];
                        mma16816(acc[mf][nf], Ah[mf], bh);
                        mma16816(acc[mf][nf], Ah[mf], bl);
                    }
            }
            __syncthreads();   // GEMM1 reads of dcur done; prev logits done

            // ---- epilogue1: bias+leaky -> fp16 H1 (overwrites dcur) ----
            #pragma unroll
            for (int mf = 0; mf < 2; mf++) {
                int r0 = mBase + mf * 16 + g;
                #pragma unroll
                for (int nf = 0; nf < 4; nf++) {
                    int o = nq * 32 + nf * 8 + 2 * tg;
                    float bb0 = b1s[o], bb1 = b1s[o + 1];
                    float x0 = acc[mf][nf][0] + bb0;
                    float x1 = acc[mf][nf][1] + bb1;
                    float x2 = acc[mf][nf][2] + bb0;
                    float x3 = acc[mf][nf][3] + bb1;
                    x0 = (x0 > 0.f) ? x0 : 0.01f * x0;
                    x1 = (x1 > 0.f) ? x1 : 0.01f * x1;
                    x2 = (x2 > 0.f) ? x2 : 0.01f * x2;
                    x3 = (x3 > 0.f) ? x3 : 0.01f * x3;
                    dcur[r0 * SW + (o >> 1)] = pack_h2(x0, x1);
                    dcur[(r0 + 8) * SW + (o >> 1)] = pack_h2(x2, x3);
                }
            }
            __syncthreads();   // H1 ready

            // ---- fused: prefetch | GEMM2 | epi2 | build D(t+1) / vis-next ----
            const float4* v4n = nullptr;
            float4 pre0, pre1, pre2, pre3;
            if (t < 3) {
                v4n = (const float4*)(vp + ((size_t)(b * NN + j0 + 128 + jb)) * NC +
                                      chb * 32);
                pre0 = v4n[0]; pre1 = v4n[1]; pre2 = v4n[2]; pre3 = v4n[3];
            }

            float acc2[2][2][4];
            #pragma unroll
            for (int mf = 0; mf < 2; mf++)
                #pragma unroll
                for (int nf = 0; nf < 2; nf++)
                    #pragma unroll
                    for (int q = 0; q < 4; q++) acc2[mf][nf][q] = 0.f;

            #pragma unroll
            for (int k = 0; k < 8; k++) {
                uint32_t Ah[2][4], Bh[4], Bl[4];
                #pragma unroll
                for (int mf = 0; mf < 2; mf++)
                    ldsm4(Ah[mf], aH0 + mf * MF_STEP + k * 32);
                ldsm4(Bh, b2H0 + k * 32);
                ldsm4(Bl, b2L0 + k * 32);
                #pragma unroll
                for (int mf = 0; mf < 2; mf++)
                    #pragma unroll
                    for (int nf = 0; nf < 2; nf++) {
                        mma16816(acc2[mf][nf], Ah[mf], &Bh[nf * 2]);
                        mma16816(acc2[mf][nf], Ah[mf], &Bl[nf * 2]);
                    }
            }

            // epi2: bias+leaky+W3 dot, cross-lane reduce into red
            {
                float lgA[2] = {0.f, 0.f}, lgB[2] = {0.f, 0.f};
                #pragma unroll
                for (int mf = 0; mf < 2; mf++)
                    #pragma unroll
                    for (int nf = 0; nf < 2; nf++) {
                        int o = nq * 16 + nf * 8 + 2 * tg;
                        float bb0 = b2s[o], bb1 = b2s[o + 1];
                        float w0 = w3s[o], w1v = w3s[o + 1];
                        float x0 = acc2[mf][nf][0] + bb0;
                        float x1 = acc2[mf][nf][1] + bb1;
                        float x2 = acc2[mf][nf][2] + bb0;
                        float x3 = acc2[mf][nf][3] + bb1;
                        x0 = (x0 > 0.f) ? x0 : 0.01f * x0;
                        x1 = (x1 > 0.f) ? x1 : 0.01f * x1;
                        x2 = (x2 > 0.f) ? x2 : 0.01f * x2;
                        x3 = (x3 > 0.f) ? x3 : 0.01f * x3;
                        lgA[mf] = fmaf(x0, w0, lgA[mf]);
                        lgA[mf] = fmaf(x1, w1v, lgA[mf]);
                        lgB[mf] = fmaf(x2, w0, lgB[mf]);
                        lgB[mf] = fmaf(x3, w1v, lgB[mf]);
                    }
                #pragma unroll
                for (int mf = 0; mf < 2; mf++) {
                    float a = lgA[mf], c = lgB[mf];
                    a += __shfl_xor_sync(0xffffffffu, a, 1);
                    a += __shfl_xor_sync(0xffffffffu, a, 2);
                    c += __shfl_xor_sync(0xffffffffu, c, 1);
                    c += __shfl_xor_sync(0xffffffffu, c, 2);
                    if (tg == 0) {
                        int r0 = mBase + mf * 16 + g;
                        red[nq * 128 + r0] = a;
                        red[nq * 128 + r0 + 8] = c;
                    }
                }
            }

            if (t < 3) {
                // build D(t+1) into the other buffer (direct + mirror ns)
                uint32_t* dn = smw + WOFF_DH0 + ((t + 1) & 1) * 128 * SW;
                float ns = 0.f;
                #pragma unroll
                for (int q = 0; q < 8; q++) {
                    float4 v = (q == 0) ? pre0 : (q == 1) ? pre1 :
                               (q == 2) ? pre2 : (q == 3) ? pre3 : v4n[q];
                    int c = chb * 32 + q * 4;
                    float d0 = visb[c] - v.x,     d1 = visb[c + 1] - v.y;
                    float d2 = visb[c + 2] - v.z, d3 = visb[c + 3] - v.w;
                    float s0 = d0 * d0, s1 = d1 * d1, s2 = d2 * d2, s3 = d3 * d3;
                    ns += (s0 + s1) + (s2 + s3);
                    int wbase = jb * SW + (c >> 1);
                    *(uint2*)&dn[wbase] = make_uint2(pack_h2(s0, s1), pack_h2(s2, s3));
                }
                ns += __shfl_xor_sync(0xffffffffu, ns, 1);
                ns += __shfl_xor_sync(0xffffffffu, ns, 2);
                if (chb == 0) {
                    int jg = j0 + 128 + jb;
                    out_ns[rowbase + jg] = -ns;
                    out_ns[((size_t)(b * NN + jg)) * NN + i] = -ns;  // mirror
                }
            } else {
                // last tile: prefetch stolen next row's vis (hidden here)
                int nrow = *nxtp;
                if (nrow < NROWS && tid < 128)
                    ((float*)(smw + WOFF_VIS))[((it + 1) & 1) * 128 + tid] =
                        vp[(size_t)nrow * NC + tid];
            }
            __syncthreads();   // red ready, D(t+1)/vis-next ready

            // logits -> raw sigmoid into g_sg (direct + transposed mirror)
            if (tid < 128) {
                int j = tid;
                float lg = b3f + red[j] + red[128 + j] + red[256 + j] + red[384 + j];
                float sg = 1.f / (1.f + expf(-lg));
                int jg = j0 + j;
                g_sg[rowbase + jg] = sg;
                g_sg[((size_t)(b * NN + jg)) * NN + i] = sg;   // mirror
            }
            // no sync: next GEMM1 reads the other D buffer; the sync after
            // GEMM1 orders this logits block before epi1 overwrites red/dcur.
        }

        row = *nxtp;   // all threads passed the red-ready sync; value stable
        it++;
    }

    // ---- self-reset of device counters for the next graph replay ----
    __syncthreads();
    if (tid == 0) {
        __threadfence();
        int d = atomicAdd(&g_done, 1);
        if (d == GRID - 1) {           // last CTA: all steals complete
            g_row_ctr = GRID;
            g_done = 0;
            __threadfence();
        }
    }
}

// ---------------- top-k + normalize (fully coalesced) ----------------
__device__ __forceinline__ float blockSum512(float v, float* redsm) {
    #pragma unroll
    for (int o = 16; o > 0; o >>= 1) v += __shfl_xor_sync(0xffffffffu, v, o);
    int w = threadIdx.x >> 5;
    __syncthreads();
    if ((threadIdx.x & 31) == 0) redsm[w] = v;
    __syncthreads();
    float s = 0.f;
    #pragma unroll
    for (int q = 0; q < 16; q++) s += redsm[q];
    return s;
}

__global__ void __launch_bounds__(512) topk_kernel(
    const float* __restrict__ epl,
    float* __restrict__ out_ep)
{
    __shared__ unsigned long long keys[2 * NN];
    __shared__ float redsm[16];
    __shared__ unsigned long long thr_s;

    const int row = blockIdx.x;
    const int i = row & (NN - 1);
    const int tid = threadIdx.x;
    const size_t rowbase = (size_t)row * NN;

    float el = epl[rowbase + tid];
    if (tid == i) el = 0.f;
    float sg = g_sg[rowbase + tid];
    float v = sg * el;

    float ep_last_sum = blockSum512(el, redsm);

    const unsigned long long mykey =
        ((unsigned long long)__float_as_uint(v) << 32) | (unsigned)(NN - 1 - tid);
    unsigned long long key = mykey;

    int pp = 0;
    for (int k = 2; k <= NN; k <<= 1) {
        int j = k >> 1;
        for (; j >= 32; j >>= 1) {
            unsigned long long* kb = keys + pp * NN;
            kb[tid] = key;
            __syncthreads();
            unsigned long long p = kb[tid ^ j];
            bool keepmin = (((tid & k) == 0) == ((tid & j) == 0));
            key = ((p < key) == keepmin) ? p : key;
            pp ^= 1;
        }
        for (; j > 0; j >>= 1) {
            unsigned long long p = __shfl_xor_sync(0xffffffffu, key, j);
            bool keepmin = (((tid & k) == 0) == ((tid & j) == 0));
            key = ((p < key) == keepmin) ? p : key;
        }
    }
    if (tid == DROPK) thr_s = key;   // sorted ascending: 52nd smallest
    __syncthreads();
    unsigned long long thr = thr_s;
    float kv = (mykey >= thr) ? v : 0.f;

    float l1 = blockSum512(kv, redsm);
    l1 = fmaxf(l1, 1e-12f);
    float o = kv / l1 * ep_last_sum;
    o += ((tid == i) ? 1.f : 0.f) + 1e-6f;
    float rs = blockSum512(o, redsm);
    out_ep[rowbase + tid] = o / rs;
}

extern "C" void kernel_launch(void* const* d_in, const int* in_sizes, int n_in,
                              void* d_out, int out_size) {
    const float* vp  = (const float*)d_in[0];
    const float* epl = (const float*)d_in[1];
    const float* W1  = (const float*)d_in[2];
    const float* g1  = (const float*)d_in[3];
    const float* be1 = (const float*)d_in[4];
    const float* m1  = (const float*)d_in[5];
    const float* v1  = (const float*)d_in[6];
    const float* W2  = (const float*)d_in[7];
    const float* g2  = (const float*)d_in[8];
    const float* be2 = (const float*)d_in[9];
    const float* m2  = (const float*)d_in[10];
    const float* v2  = (const float*)d_in[11];
    const float* W3  = (const float*)d_in[12];
    const float* b3  = (const float*)d_in[13];

    float* out_ep = (float*)d_out;
    float* out_ns = (float*)d_out + NB * NN * NN;

    cudaFuncSetAttribute(mlp_kernel, cudaFuncAttributeMaxDynamicSharedMemorySize,
                         SMEM_TOTAL);

    mlp_kernel<<<GRID, 512, SMEM_TOTAL>>>(vp, W1, g1, be1, m1, v1,
                                          W2, g2, be2, m2, v2, W3, b3, out_ns);
    topk_kernel<<<NROWS, 512>>>(epl, out_ep);
}

// round 17
// speedup vs baseline: 1.0508x; 1.0154x over previous
#include <cuda_runtime.h>
#include <cuda_fp16.h>
#include <math.h>
#include <stdint.h>

#define NB 2
#define NN 512
#define NC 128
#define O1 128
#define O2 64
#define DROPK 52         // 512 - 460
#define SW 68            // row stride in u32 words (136 fp16; ldmatrix conflict-free)
#define NROWS (NB * NN)
#define GRID 148

__device__ __forceinline__ uint32_t smem_u32(const void* p) {
    uint32_t a;
    asm("{ .reg .u64 t; cvta.to.shared.u64 t, %1; cvt.u32.u64 %0, t; }"
        : "=r"(a) : "l"(p));
    return a;
}

// pack two fp32 into fp16x2 (lo = x0, hi = x1)
__device__ __forceinline__ uint32_t pack_h2(float x0, float x1) {
    uint32_t r;
    asm("cvt.rn.f16x2.f32 %0, %1, %2;" : "=r"(r) : "f"(x1), "f"(x0));
    return r;
}
// pack + residual (for weights)
__device__ __forceinline__ void split2h(float x0, float x1, uint32_t& hp, uint32_t& lp) {
    hp = pack_h2(x0, x1);
    __half2 hb = *reinterpret_cast<__half2*>(&hp);
    float l0 = x0 - __half2float(hb.x);
    float l1 = x1 - __half2float(hb.y);
    lp = pack_h2(l0, l1);
}

__device__ __forceinline__ void mma16816(float* c, const uint32_t* a, const uint32_t* b) {
    asm volatile(
        "mma.sync.aligned.m16n8k16.row.col.f32.f16.f16.f32 "
        "{%0,%1,%2,%3}, {%4,%5,%6,%7}, {%8,%9}, {%0,%1,%2,%3};"
        : "+f"(c[0]), "+f"(c[1]), "+f"(c[2]), "+f"(c[3])
        : "r"(a[0]), "r"(a[1]), "r"(a[2]), "r"(a[3]), "r"(b[0]), "r"(b[1]));
}

__device__ __forceinline__ void ldsm4(uint32_t* r, uint32_t saddr) {
    asm volatile("ldmatrix.sync.aligned.m8n8.x4.shared.b16 {%0,%1,%2,%3}, [%4];"
                 : "=r"(r[0]), "=r"(r[1]), "=r"(r[2]), "=r"(r[3]) : "r"(saddr));
}

// group-scoped barrier: 4 warps (128 threads) of m-group mg, barrier id 1+mg
#define BARG(mg) asm volatile("bar.sync %0, 128;" :: "r"(1 + (mg)) : "memory")

// ---------------- device state ----------------
__device__ int g_row_ctr = GRID;   // work-steal counter (self-resetting)
__device__ int g_done = 0;         // completion counter (self-resetting)
// raw sigmoid(logits); fully populated (direct + transposed mirror writes).
__device__ float g_sg[(size_t)NB * NN * NN];

// ---------------- SMEM layout (u32 word offsets) ----------------
#define WOFF_VIS  0                       // 2 x 128 (double-buffered vis)
#define WOFF_B1   256
#define WOFF_B2   384
#define WOFF_W3   448
#define WOFF_B3   512                     // 1
#define WOFF_NXT  513                     // 1 (next stolen row)
#define WOFF_RED  516                     // 2 x 512 (double-buffered; also s1/s2 scratch)
#define WOFF_W1H  1540
#define WOFF_W1L  (WOFF_W1H + O1 * SW)
#define WOFF_W2H  (WOFF_W1L + O1 * SW)
#define WOFF_W2L  (WOFF_W2H + O2 * SW)
#define WOFF_DH0  (WOFF_W2L + O2 * SW)    // D buffer 0
#define WOFF_DH1  (WOFF_DH0 + 128 * SW)   // D buffer 1
#define WTOT      (WOFF_DH1 + 128 * SW)
#define SMEM_TOTAL (WTOT * 4)             // ~180 KB

__global__ void __launch_bounds__(512, 1) mlp_kernel(
    const float* __restrict__ vp,       // [B,N,C]
    const float* __restrict__ W1, const float* __restrict__ g1,
    const float* __restrict__ be1, const float* __restrict__ m1,
    const float* __restrict__ v1,
    const float* __restrict__ W2, const float* __restrict__ g2,
    const float* __restrict__ be2, const float* __restrict__ m2,
    const float* __restrict__ v2,
    const float* __restrict__ W3, const float* __restrict__ b3,
    float* __restrict__ out_ns)         // [B,N,N] (direct + mirror writes)
{
    extern __shared__ __align__(16) uint32_t smw[];
    const int tid = threadIdx.x;
    const int lid = tid & 31;
    const int g = lid >> 2;
    const int tg = lid & 3;
    const int wid = tid >> 5;
    const int nq = wid & 3;            // 4 n-groups
    const int mg = wid >> 2;           // m-group 0..3
    const int mBase = mg * 32;         // 32 m-rows per group

    float* b1s = (float*)(smw + WOFF_B1);
    float* b2s = (float*)(smw + WOFF_B2);
    float* w3s = (float*)(smw + WOFF_W3);
    float* red = (float*)(smw + WOFF_RED);
    int* nxtp = (int*)(smw + WOFF_NXT);

    const uint32_t smb = smem_u32(smw);

    // ldmatrix per-lane row offsets (words)
    const int laneA = (lid < 16) ? lid * SW : (lid - 16) * SW + 4;
    int laneB;   // {nlo/klo, nlo/khi, nhi/klo, nhi/khi}
    if (lid < 8)       laneB = lid * SW;
    else if (lid < 16) laneB = (lid - 8) * SW + 4;
    else if (lid < 24) laneB = (lid - 8) * SW;
    else               laneB = (lid - 16) * SW + 4;

    const uint32_t aBase0 = smb + (uint32_t)(WOFF_DH0 + mBase * SW + laneA) * 4;
    const uint32_t DBUF_STEP = 128u * SW * 4u;
    const uint32_t b1H0 = smb + (uint32_t)(WOFF_W1H + nq * 32 * SW + laneB) * 4;
    const uint32_t b1L0 = smb + (uint32_t)(WOFF_W1L + nq * 32 * SW + laneB) * 4;
    const uint32_t b2H0 = smb + (uint32_t)(WOFF_W2H + nq * 16 * SW + laneB) * 4;
    const uint32_t b2L0 = smb + (uint32_t)(WOFF_W2L + nq * 16 * SW + laneB) * 4;
    const uint32_t MF_STEP = 16 * SW * 4;
    const uint32_t NT_STEP = 16 * SW * 4;

    // ---- prologue phase 1: scales, biases, first-row vis ----
    if (tid < NC) {
        float s = g1[tid] / sqrtf(v1[tid] + 1e-5f);
        red[tid] = s;                      // s1
        b1s[tid] = be1[tid] - m1[tid] * s;
        ((float*)(smw + WOFF_VIS))[tid] = vp[(size_t)blockIdx.x * NC + tid];
    } else if (tid < NC + O2) {
        int o = tid - NC;
        float s = g2[o] / sqrtf(v2[o] + 1e-5f);
        red[O1 + o] = s;                   // s2
        b2s[o] = be2[o] - m2[o] * s;
        w3s[o] = W3[o];
        if (o == 0) ((float*)(smw + WOFF_B3))[0] = b3[0];
    }
    __syncthreads();

    // ---- prologue phase 2: fold + split weights directly into smem ----
    for (int idx = tid; idx < O1 * 64; idx += 512) {
        int o = idx >> 6, cp = idx & 63;
        float2 w = *(const float2*)&W1[o * NC + 2 * cp];
        float s = red[o];
        uint32_t hp, lp;
        split2h(w.x * s, w.y * s, hp, lp);
        smw[WOFF_W1H + o * SW + cp] = hp;
        smw[WOFF_W1L + o * SW + cp] = lp;
    }
    for (int idx = tid; idx < O2 * 64; idx += 512) {
        int n = idx >> 6, cp = idx & 63;
        float2 w = *(const float2*)&W2[n * O1 + 2 * cp];
        float s = red[O1 + n];
        uint32_t hp, lp;
        split2h(w.x * s, w.y * s, hp, lp);
        smw[WOFF_W2H + n * SW + cp] = hp;
        smw[WOFF_W2L + n * SW + cp] = lp;
    }
    __syncthreads();
    const float b3f = ((float*)(smw + WOFF_B3))[0];

    const int jb = tid >> 2;        // D-build: j within tile
    const int chb = tid & 3;        // channel quarter

    int row = blockIdx.x;           // initial static assignment
    int it = 0;
    while (row < NROWS) {
        const int b = row >> 9;
        const int i = row & (NN - 1);
        const int bi = i >> 7;              // first tile index
        const size_t rowbase = (size_t)row * NN;
        float* visb = (float*)(smw + WOFF_VIS) + (it & 1) * 128;

        // steal the NEXT row now; barriers separate this from its readers.
        if (tid == 0) *nxtp = atomicAdd(&g_row_ctr, 1);

        // ---- prologue: build D(bi) + node similarity (direct + mirror) ----
        {
            uint32_t* dn = smw + WOFF_DH0 + (bi & 1) * 128 * SW;
            const int jg0 = bi * 128;
            const float4* v4 =
                (const float4*)(vp + ((size_t)(b * NN + jg0 + jb)) * NC + chb * 32);
            float ns = 0.f;
            #pragma unroll
            for (int q = 0; q < 8; q++) {
                float4 v = v4[q];
                int c = chb * 32 + q * 4;
                float d0 = visb[c] - v.x,     d1 = visb[c + 1] - v.y;
                float d2 = visb[c + 2] - v.z, d3 = visb[c + 3] - v.w;
                float s0 = d0 * d0, s1 = d1 * d1, s2 = d2 * d2, s3 = d3 * d3;
                ns += (s0 + s1) + (s2 + s3);
                int wbase = jb * SW + (c >> 1);
                *(uint2*)&dn[wbase] = make_uint2(pack_h2(s0, s1), pack_h2(s2, s3));
            }
            ns += __shfl_xor_sync(0xffffffffu, ns, 1);
            ns += __shfl_xor_sync(0xffffffffu, ns, 2);
            if (chb == 0) {
                int jg = jg0 + jb;
                out_ns[rowbase + jg] = -ns;
                out_ns[((size_t)(b * NN + jg)) * NN + i] = -ns;  // mirror
            }
        }
        __syncthreads();

        for (int t = bi; t < 4; t++) {
            const int j0 = t * 128;
            const uint32_t aH0 = aBase0 + (uint32_t)(t & 1) * DBUF_STEP;
            uint32_t* dcur = smw + WOFF_DH0 + (t & 1) * 128 * SW;
            float* redb = red + (t & 1) * 512;   // double-buffered logit partials

            // ---- GEMM1: 2-pass fp16 (Ah*Bh + Ah*Bl) ----
            float acc[2][4][4];
            #pragma unroll
            for (int mf = 0; mf < 2; mf++)
                #pragma unroll
                for (int nf = 0; nf < 4; nf++)
                    #pragma unroll
                    for (int q = 0; q < 4; q++) acc[mf][nf][q] = 0.f;

            #pragma unroll
            for (int k = 0; k < 8; k++) {
                uint32_t Ah[2][4], Bh[2][4], Bl[2][4];
                #pragma unroll
                for (int mf = 0; mf < 2; mf++)
                    ldsm4(Ah[mf], aH0 + mf * MF_STEP + k * 32);
                #pragma unroll
                for (int nt = 0; nt < 2; nt++) {
                    ldsm4(Bh[nt], b1H0 + nt * NT_STEP + k * 32);
                    ldsm4(Bl[nt], b1L0 + nt * NT_STEP + k * 32);
                }
                #pragma unroll
                for (int mf = 0; mf < 2; mf++)
                    #pragma unroll
                    for (int nf = 0; nf < 4; nf++) {
                        const uint32_t* bh = &Bh[nf >> 1][(nf & 1) * 2];
                        const uint32_t* bl = &Bl[nf >> 1][(nf & 1) * 2];
                        mma16816(acc[mf][nf], Ah[mf], bh);
                        mma16816(acc[mf][nf], Ah[mf], bl);
                    }
            }
            BARG(mg);   // group's reads of dcur rows [mBase,mBase+32) done

            // ---- epilogue1: bias+leaky -> fp16 H1 (overwrites dcur rows) ----
            #pragma unroll
            for (int mf = 0; mf < 2; mf++) {
                int r0 = mBase + mf * 16 + g;
                #pragma unroll
                for (int nf = 0; nf < 4; nf++) {
                    int o = nq * 32 + nf * 8 + 2 * tg;
                    float bb0 = b1s[o], bb1 = b1s[o + 1];
                    float x0 = acc[mf][nf][0] + bb0;
                    float x1 = acc[mf][nf][1] + bb1;
                    float x2 = acc[mf][nf][2] + bb0;
                    float x3 = acc[mf][nf][3] + bb1;
                    x0 = (x0 > 0.f) ? x0 : 0.01f * x0;
                    x1 = (x1 > 0.f) ? x1 : 0.01f * x1;
                    x2 = (x2 > 0.f) ? x2 : 0.01f * x2;
                    x3 = (x3 > 0.f) ? x3 : 0.01f * x3;
                    dcur[r0 * SW + (o >> 1)] = pack_h2(x0, x1);
                    dcur[(r0 + 8) * SW + (o >> 1)] = pack_h2(x2, x3);
                }
            }
            BARG(mg);   // group's H1 rows ready

            // ---- fused: prefetch | GEMM2 | epi2 | build D(t+1) / vis-next ----
            const float4* v4n = nullptr;
            float4 pre0, pre1, pre2, pre3;
            if (t < 3) {
                v4n = (const float4*)(vp + ((size_t)(b * NN + j0 + 128 + jb)) * NC +
                                      chb * 32);
                pre0 = v4n[0]; pre1 = v4n[1]; pre2 = v4n[2]; pre3 = v4n[3];
            }

            float acc2[2][2][4];
            #pragma unroll
            for (int mf = 0; mf < 2; mf++)
                #pragma unroll
                for (int nf = 0; nf < 2; nf++)
                    #pragma unroll
                    for (int q = 0; q < 4; q++) acc2[mf][nf][q] = 0.f;

            #pragma unroll
            for (int k = 0; k < 8; k++) {
                uint32_t Ah[2][4], Bh[4], Bl[4];
                #pragma unroll
                for (int mf = 0; mf < 2; mf++)
                    ldsm4(Ah[mf], aH0 + mf * MF_STEP + k * 32);
                ldsm4(Bh, b2H0 + k * 32);
                ldsm4(Bl, b2L0 + k * 32);
                #pragma unroll
                for (int mf = 0; mf < 2; mf++)
                    #pragma unroll
                    for (int nf = 0; nf < 2; nf++) {
                        mma16816(acc2[mf][nf], Ah[mf], &Bh[nf * 2]);
                        mma16816(acc2[mf][nf], Ah[mf], &Bl[nf * 2]);
                    }
            }

            // epi2: bias+leaky+W3 dot, cross-lane reduce into redb
            {
                float lgA[2] = {0.f, 0.f}, lgB[2] = {0.f, 0.f};
                #pragma unroll
                for (int mf = 0; mf < 2; mf++)
                    #pragma unroll
                    for (int nf = 0; nf < 2; nf++) {
                        int o = nq * 16 + nf * 8 + 2 * tg;
                        float bb0 = b2s[o], bb1 = b2s[o + 1];
                        float w0 = w3s[o], w1v = w3s[o + 1];
                        float x0 = acc2[mf][nf][0] + bb0;
                        float x1 = acc2[mf][nf][1] + bb1;
                        float x2 = acc2[mf][nf][2] + bb0;
                        float x3 = acc2[mf][nf][3] + bb1;
                        x0 = (x0 > 0.f) ? x0 : 0.01f * x0;
                        x1 = (x1 > 0.f) ? x1 : 0.01f * x1;
                        x2 = (x2 > 0.f) ? x2 : 0.01f * x2;
                        x3 = (x3 > 0.f) ? x3 : 0.01f * x3;
                        lgA[mf] = fmaf(x0, w0, lgA[mf]);
                        lgA[mf] = fmaf(x1, w1v, lgA[mf]);
                        lgB[mf] = fmaf(x2, w0, lgB[mf]);
                        lgB[mf] = fmaf(x3, w1v, lgB[mf]);
                    }
                #pragma unroll
                for (int mf = 0; mf < 2; mf++) {
                    float a = lgA[mf], c = lgB[mf];
                    a += __shfl_xor_sync(0xffffffffu, a, 1);
                    a += __shfl_xor_sync(0xffffffffu, a, 2);
                    c += __shfl_xor_sync(0xffffffffu, c, 1);
                    c += __shfl_xor_sync(0xffffffffu, c, 2);
                    if (tg == 0) {
                        int r0 = mBase + mf * 16 + g;
                        redb[nq * 128 + r0] = a;
                        redb[nq * 128 + r0 + 8] = c;
                    }
                }
            }

            if (t < 3) {
                // build D(t+1) into the other buffer (direct + mirror ns)
                uint32_t* dn = smw + WOFF_DH0 + ((t + 1) & 1) * 128 * SW;
                float ns = 0.f;
                #pragma unroll
                for (int q = 0; q < 8; q++) {
                    float4 v = (q == 0) ? pre0 : (q == 1) ? pre1 :
                               (q == 2) ? pre2 : (q == 3) ? pre3 : v4n[q];
                    int c = chb * 32 + q * 4;
                    float d0 = visb[c] - v.x,     d1 = visb[c + 1] - v.y;
                    float d2 = visb[c + 2] - v.z, d3 = visb[c + 3] - v.w;
                    float s0 = d0 * d0, s1 = d1 * d1, s2 = d2 * d2, s3 = d3 * d3;
                    ns += (s0 + s1) + (s2 + s3);
                    int wbase = jb * SW + (c >> 1);
                    *(uint2*)&dn[wbase] = make_uint2(pack_h2(s0, s1), pack_h2(s2, s3));
                }
                ns += __shfl_xor_sync(0xffffffffu, ns, 1);
                ns += __shfl_xor_sync(0xffffffffu, ns, 2);
                if (chb == 0) {
                    int jg = j0 + 128 + jb;
                    out_ns[rowbase + jg] = -ns;
                    out_ns[((size_t)(b * NN + jg)) * NN + i] = -ns;  // mirror
                }
            } else {
                // last tile: prefetch stolen next row's vis (hidden here)
                int nrow = *nxtp;
                if (nrow < NROWS && tid < 128)
                    ((float*)(smw + WOFF_VIS))[((it + 1) & 1) * 128 + tid] =
                        vp[(size_t)nrow * NC + tid];
            }
            __syncthreads();   // redb ready, D(t+1)/vis-next ready (cross-group)

            // logits -> raw sigmoid into g_sg (direct + transposed mirror)
            // redb is parity-buffered: epi2 of the next tile writes the OTHER
            // buffer, and the next full sync separates same-buffer reuse.
            if (tid < 128) {
                int j = tid;
                float lg = b3f + redb[j] + redb[128 + j] + redb[256 + j] +
                           redb[384 + j];
                float sg = 1.f / (1.f + expf(-lg));
                int jg = j0 + j;
                g_sg[rowbase + jg] = sg;
                g_sg[((size_t)(b * NN + jg)) * NN + i] = sg;   // mirror
            }
        }

        row = *nxtp;   // all threads passed the phase3 full sync; value stable
        it++;
    }

    // ---- self-reset of device counters for the next graph replay ----
    __syncthreads();
    if (tid == 0) {
        __threadfence();
        int d = atomicAdd(&g_done, 1);
        if (d == GRID - 1) {           // last CTA: all steals complete
            g_row_ctr = GRID;
            g_done = 0;
            __threadfence();
        }
    }
}

// ---------------- top-k + normalize (fully coalesced) ----------------
__device__ __forceinline__ float blockSum512(float v, float* redsm) {
    #pragma unroll
    for (int o = 16; o > 0; o >>= 1) v += __shfl_xor_sync(0xffffffffu, v, o);
    int w = threadIdx.x >> 5;
    __syncthreads();
    if ((threadIdx.x & 31) == 0) redsm[w] = v;
    __syncthreads();
    float s = 0.f;
    #pragma unroll
    for (int q = 0; q < 16; q++) s += redsm[q];
    return s;
}

__global__ void __launch_bounds__(512) topk_kernel(
    const float* __restrict__ epl,
    float* __restrict__ out_ep)
{
    __shared__ unsigned long long keys[2 * NN];
    __shared__ float redsm[16];
    __shared__ unsigned long long thr_s;

    const int row = blockIdx.x;
    const int i = row & (NN - 1);
    const int tid = threadIdx.x;
    const size_t rowbase = (size_t)row * NN;

    float el = epl[rowbase + tid];
    if (tid == i) el = 0.f;
    float sg = g_sg[rowbase + tid];
    float v = sg * el;

    float ep_last_sum = blockSum512(el, redsm);

    const unsigned long long mykey =
        ((unsigned long long)__float_as_uint(v) << 32) | (unsigned)(NN - 1 - tid);
    unsigned long long key = mykey;

    int pp = 0;
    for (int k = 2; k <= NN; k <<= 1) {
        int j = k >> 1;
        for (; j >= 32; j >>= 1) {
            unsigned long long* kb = keys + pp * NN;
            kb[tid] = key;
            __syncthreads();
            unsigned long long p = kb[tid ^ j];
            bool keepmin = (((tid & k) == 0) == ((tid & j) == 0));
            key = ((p < key) == keepmin) ? p : key;
            pp ^= 1;
        }
        for (; j > 0; j >>= 1) {
            unsigned long long p = __shfl_xor_sync(0xffffffffu, key, j);
            bool keepmin = (((tid & k) == 0) == ((tid & j) == 0));
            key = ((p < key) == keepmin) ? p : key;
        }
    }
    if (tid == DROPK) thr_s = key;   // sorted ascending: 52nd smallest
    __syncthreads();
    unsigned long long thr = thr_s;
    float kv = (mykey >= thr) ? v : 0.f;

    float l1 = blockSum512(kv, redsm);
    l1 = fmaxf(l1, 1e-12f);
    float o = kv / l1 * ep_last_sum;
    o += ((tid == i) ? 1.f : 0.f) + 1e-6f;
    float rs = blockSum512(o, redsm);
    out_ep[rowbase + tid] = o / rs;
}

extern "C" void kernel_launch(void* const* d_in, const int* in_sizes, int n_in,
                              void* d_out, int out_size) {
    const float* vp  = (const float*)d_in[0];
    const float* epl = (const float*)d_in[1];
    const float* W1  = (const float*)d_in[2];
    const float* g1  = (const float*)d_in[3];
    const float* be1 = (const float*)d_in[4];
    const float* m1  = (const float*)d_in[5];
    const float* v1  = (const float*)d_in[6];
    const float* W2  = (const float*)d_in[7];
    const float* g2  = (const float*)d_in[8];
    const float* be2 = (const float*)d_in[9];
    const float* m2  = (const float*)d_in[10];
    const float* v2  = (const float*)d_in[11];
    const float* W3  = (const float*)d_in[12];
    const float* b3  = (const float*)d_in[13];

    float* out_ep = (float*)d_out;
    float* out_ns = (float*)d_out + NB * NN * NN;

    cudaFuncSetAttribute(mlp_kernel, cudaFuncAttributeMaxDynamicSharedMemorySize,
                         SMEM_TOTAL);

    mlp_kernel<<<GRID, 512, SMEM_TOTAL>>>(vp, W1, g1, be1, m1, v1,
                                          W2, g2, be2, m2, v2, W3, b3, out_ns);
    topk_kernel<<<NROWS, 512>>>(epl, out_ep);
}